// round 1
// baseline (speedup 1.0000x reference)
#include <cuda_runtime.h>

#define BB 128
#define TT 2048
#define DD 64
#define HH 128
#define OO 32

// Scratch (allocation-free rule: __device__ globals)
__device__ float g_xp0[(size_t)BB * TT * HH];  // layer0 input projection
__device__ float g_h1[(size_t)BB * TT * HH];   // layer1 hidden states

// ---------------------------------------------------------------------------
// fast tanh: ~1e-7 relative error, ~10 instructions
__device__ __forceinline__ float fast_tanh(float x) {
    float ax = fminf(fabsf(x), 9.0f);          // tanh(9) == 1 to fp32
    float e  = __expf(2.0f * ax);              // e <= e^18 ~ 6.6e7, safe for fdividef
    float r  = 1.0f - __fdividef(2.0f, e + 1.0f);
    return copysignf(r, x);
}

// 128-long dot product: weights live in registers as 64 packed f32x2 values,
// vector v comes from shared memory via LDS.128 (ulonglong2).
__device__ __forceinline__ float dot128(const unsigned long long* w, const float* v) {
    unsigned long long acc0 = 0ull, acc1 = 0ull;  // packed (0.0f, 0.0f)
    const ulonglong2* v2 = (const ulonglong2*)v;
#pragma unroll
    for (int j = 0; j < 32; j++) {
        ulonglong2 hv = v2[j];
        asm("fma.rn.f32x2 %0, %1, %2, %0;" : "+l"(acc0) : "l"(w[2 * j]),     "l"(hv.x));
        asm("fma.rn.f32x2 %0, %1, %2, %0;" : "+l"(acc1) : "l"(w[2 * j + 1]), "l"(hv.y));
    }
    float l0 = __uint_as_float((unsigned)(acc0 & 0xffffffffu));
    float h0 = __uint_as_float((unsigned)(acc0 >> 32));
    float l1 = __uint_as_float((unsigned)(acc1 & 0xffffffffu));
    float h1 = __uint_as_float((unsigned)(acc1 >> 32));
    return (l0 + h0) + (l1 + h1);
}

// ---------------------------------------------------------------------------
// Kernel 1: xp0[b,t,h] = sum_d x[b,t,d]*W_ih0[h,d] + b_ih0[h] + b_hh0[h]
// Block = 32 (b,t) rows, 256 threads. Each thread: 2 output columns x 8 rows,
// W rows in registers, x tile in smem (broadcast reads).
__global__ void __launch_bounds__(256)
xproj_kernel(const float* __restrict__ x, const float* __restrict__ Wih0,
             const float* __restrict__ bih0, const float* __restrict__ bhh0) {
    __shared__ __align__(16) float xs[32 * DD];
    int row0 = blockIdx.x * 32;
    const float4* xg = (const float4*)(x + (size_t)row0 * DD);
    float4* xs4 = (float4*)xs;
    xs4[threadIdx.x]       = xg[threadIdx.x];
    xs4[threadIdx.x + 256] = xg[threadIdx.x + 256];

    int h2   = threadIdx.x & 63;   // column pair -> columns 2*h2, 2*h2+1
    int quad = threadIdx.x >> 6;   // rows quad*8 .. +8
    float w0[DD], w1[DD];
    const float4* wg0 = (const float4*)(Wih0 + (size_t)(2 * h2) * DD);
    const float4* wg1 = (const float4*)(Wih0 + (size_t)(2 * h2 + 1) * DD);
#pragma unroll
    for (int j = 0; j < 16; j++) {
        float4 t0 = wg0[j];
        w0[4 * j] = t0.x; w0[4 * j + 1] = t0.y; w0[4 * j + 2] = t0.z; w0[4 * j + 3] = t0.w;
        float4 t1 = wg1[j];
        w1[4 * j] = t1.x; w1[4 * j + 1] = t1.y; w1[4 * j + 2] = t1.z; w1[4 * j + 3] = t1.w;
    }
    float bias0 = bih0[2 * h2]     + bhh0[2 * h2];
    float bias1 = bih0[2 * h2 + 1] + bhh0[2 * h2 + 1];
    __syncthreads();

#pragma unroll
    for (int r = 0; r < 8; r++) {
        int rr = quad * 8 + r;
        float a0 = bias0, a1 = bias1;
#pragma unroll
        for (int d = 0; d < DD; d++) {
            float xv = xs[rr * DD + d];
            a0 = fmaf(w0[d], xv, a0);
            a1 = fmaf(w1[d], xv, a1);
        }
        ((float2*)g_xp0)[(size_t)(row0 + rr) * (HH / 2) + h2] = make_float2(a0, a1);
    }
}

// ---------------------------------------------------------------------------
// Kernel 2: the sequential scan. 1 CTA per batch element, 384 threads:
//   group 0 (tid   0..127): layer0 recurrence, holds W_hh0 row in regs
//   group 1 (tid 128..255): layer1 input proj, holds W_ih1 row in regs
//   group 2 (tid 256..383): layer1 recurrence, holds W_hh1 row in regs
// Software pipeline with 1-step skew per group; one barrier per iteration.
// Iteration s: A computes h0[s], B computes p1[s-1], C computes h1[s-2].
__global__ void __launch_bounds__(384, 1)
scan_kernel(const float* __restrict__ Whh0, const float* __restrict__ Wih1,
            const float* __restrict__ Whh1, const float* __restrict__ bih1,
            const float* __restrict__ bhh1, const int* __restrict__ lengths) {
    __shared__ __align__(16) float h0buf[2][HH];
    __shared__ __align__(16) float h1buf[2][HH];
    __shared__ __align__(16) float p1buf[2][HH];

    int b   = blockIdx.x;
    int L   = lengths[b];
    int tid = threadIdx.x;
    int grp = tid >> 7;
    int row = tid & 127;

    const float* Wrow = (grp == 0 ? Whh0 : (grp == 1 ? Wih1 : Whh1)) + (size_t)row * HH;
    unsigned long long w[64];
#pragma unroll
    for (int j = 0; j < 64; j++) w[j] = ((const unsigned long long*)Wrow)[j];

    float bias1 = 0.f;
    if (grp == 1) bias1 = bih1[row] + bhh1[row];

    // value index -1 (initial zero state) lives in buffer 1
    if (grp == 0) h0buf[1][row] = 0.f;
    if (grp == 2) h1buf[1][row] = 0.f;

    const float* xp_base = g_xp0 + (size_t)b * TT * HH + row;
    float* h1_out_base   = g_h1  + (size_t)b * TT * HH + row;
    float xp_cur = 0.f;
    if (grp == 0 && L > 0) xp_cur = xp_base[0];

    __syncthreads();

    int send = L + 2;
    for (int s = 0; s < send; s++) {
        int pa = s & 1, pb = pa ^ 1;
        if (grp == 0) {
            if (s < L) {
                float xp_next = 0.f;
                if (s + 1 < L) xp_next = xp_base[(size_t)(s + 1) * HH];  // prefetch
                float v = xp_cur + dot128(w, h0buf[pb]);   // reads h0 value s-1
                h0buf[pa][row] = fast_tanh(v);             // writes h0 value s
                xp_cur = xp_next;
            }
        } else if (grp == 1) {
            if (s >= 1 && s <= L) {
                float v = bias1 + dot128(w, h0buf[pb]);    // reads h0 value s-1
                p1buf[pb][row] = v;                        // writes p1 value s-1
            }
        } else {
            if (s >= 2) {  // s <= L+1 guaranteed by loop bound
                float v  = p1buf[pa][row] + dot128(w, h1buf[pb]);  // p1[s-2], h1[s-3]
                float hn = fast_tanh(v);
                h1buf[pa][row] = hn;                       // writes h1 value s-2
                h1_out_base[(size_t)(s - 2) * HH] = hn;
            }
        }
        __syncthreads();
    }
}

// ---------------------------------------------------------------------------
// Kernel 3: out[b,t,:] = (t < L) ? h1[b,t,:] @ W_fc^T + b_fc : b_fc
// Block = 8 (b,t) rows, 256 threads = 8 rows x 32 outputs. W_fc transposed in
// smem with pad 33 -> conflict-free; h1 reads are warp-broadcast.
__global__ void __launch_bounds__(256)
fc_kernel(const float* __restrict__ Wfc, const float* __restrict__ bfc,
          const int* __restrict__ lengths, float* __restrict__ out) {
    __shared__ __align__(16) float wfcT[HH * 33];
    __shared__ __align__(16) float h1s[8 * HH];
    __shared__ float bfcs[OO];

    int row0 = blockIdx.x * 8;       // 8 | TT, so whole block is one batch b
    int b = row0 / TT;
    int L = lengths[b];

    for (int idx = threadIdx.x; idx < OO * HH; idx += 256) {
        int o = idx >> 7, k = idx & 127;
        wfcT[k * 33 + o] = Wfc[idx];
    }
    if (threadIdx.x < OO) bfcs[threadIdx.x] = bfc[threadIdx.x];
    const float4* hg = (const float4*)(g_h1 + (size_t)row0 * HH);
    ((float4*)h1s)[threadIdx.x] = hg[threadIdx.x];
    __syncthreads();

    int o = threadIdx.x & 31;
    int r = threadIdx.x >> 5;
    int t = (row0 % TT) + r;
    float res;
    if (t < L) {
        float acc = 0.f;
#pragma unroll
        for (int k = 0; k < HH; k++)
            acc = fmaf(wfcT[k * 33 + o], h1s[r * HH + k], acc);
        res = acc + bfcs[o];
    } else {
        res = bfcs[o];
    }
    out[(size_t)(row0 + r) * OO + o] = res;
}

// ---------------------------------------------------------------------------
extern "C" void kernel_launch(void* const* d_in, const int* in_sizes, int n_in,
                              void* d_out, int out_size) {
    const float* x     = (const float*)d_in[0];
    const int*   len   = (const int*)  d_in[1];
    const float* Wih0  = (const float*)d_in[2];
    const float* Whh0  = (const float*)d_in[3];
    const float* bih0  = (const float*)d_in[4];
    const float* bhh0  = (const float*)d_in[5];
    const float* Wih1  = (const float*)d_in[6];
    const float* Whh1  = (const float*)d_in[7];
    const float* bih1  = (const float*)d_in[8];
    const float* bhh1  = (const float*)d_in[9];
    const float* Wfc   = (const float*)d_in[10];
    const float* bfc   = (const float*)d_in[11];
    float* out = (float*)d_out;

    xproj_kernel<<<(BB * TT) / 32, 256>>>(x, Wih0, bih0, bhh0);
    scan_kernel<<<BB, 384>>>(Whh0, Wih1, Whh1, bih1, bhh1, len);
    fc_kernel<<<(BB * TT) / 8, 256>>>(Wfc, bfc, len, out);
}

// round 2
// speedup vs baseline: 1.4419x; 1.4419x over previous
#include <cuda_runtime.h>

#define BB 128
#define TT 2048
#define DD 64
#define HH 128
#define OO 32

typedef unsigned long long ull;

// Scratch (allocation-free rule: __device__ globals)
__device__ float g_xp0[(size_t)BB * TT * HH];  // layer0 input projection
__device__ float g_h1[(size_t)BB * TT * HH];   // layer1 hidden states

// ---------------------------------------------------------------------------
// fast tanh: ~1e-7 relative error
__device__ __forceinline__ float fast_tanh(float x) {
    float ax = fminf(fabsf(x), 9.0f);
    float e  = __expf(2.0f * ax);
    float r  = 1.0f - __fdividef(2.0f, e + 1.0f);
    return copysignf(r, x);
}

// 128-long dot product: weights in registers as 64 packed f32x2, vector from
// smem via LDS.128. 4 independent accumulator chains (16-deep each), packed
// f32x2 reduction.
__device__ __forceinline__ float dot128(const ull* w, const float* v) {
    ull a0 = 0ull, a1 = 0ull, a2 = 0ull, a3 = 0ull;
    const ulonglong2* v2 = (const ulonglong2*)v;
#pragma unroll
    for (int j = 0; j < 16; j++) {
        ulonglong2 p = v2[2 * j];
        ulonglong2 q = v2[2 * j + 1];
        asm("fma.rn.f32x2 %0, %1, %2, %0;" : "+l"(a0) : "l"(w[4 * j]),     "l"(p.x));
        asm("fma.rn.f32x2 %0, %1, %2, %0;" : "+l"(a1) : "l"(w[4 * j + 1]), "l"(p.y));
        asm("fma.rn.f32x2 %0, %1, %2, %0;" : "+l"(a2) : "l"(w[4 * j + 2]), "l"(q.x));
        asm("fma.rn.f32x2 %0, %1, %2, %0;" : "+l"(a3) : "l"(w[4 * j + 3]), "l"(q.y));
    }
    asm("add.rn.f32x2 %0, %0, %1;" : "+l"(a0) : "l"(a1));
    asm("add.rn.f32x2 %0, %0, %1;" : "+l"(a2) : "l"(a3));
    asm("add.rn.f32x2 %0, %0, %1;" : "+l"(a0) : "l"(a2));
    float lo = __uint_as_float((unsigned)(a0 & 0xffffffffu));
    float hi = __uint_as_float((unsigned)(a0 >> 32));
    return lo + hi;
}

// ---------------------------------------------------------------------------
// Kernel 1: xp0[b,t,h] = sum_d x[b,t,d]*W_ih0[h,d] + b_ih0[h] + b_hh0[h]
// Proper smem-tiled GEMM: block tile = 128 (b,t) rows x 128 h cols, K = 64.
// x^T and W^T staged in dynamic smem (pad 132 -> conflict-free f4 reads),
// 8x8 register tile per thread (256 threads).
#define XPAD 132
__global__ void __launch_bounds__(256)
xproj_kernel(const float* __restrict__ x, const float* __restrict__ Wih0,
             const float* __restrict__ bih0, const float* __restrict__ bhh0) {
    extern __shared__ float sm[];
    float* xsT = sm;                 // [64][XPAD] : xsT[d][r]
    float* wsT = sm + 64 * XPAD;     // [64][XPAD] : wsT[d][h]
    int tid  = threadIdx.x;
    int row0 = blockIdx.x * 128;

    const float4* xg = (const float4*)(x + (size_t)row0 * DD);
#pragma unroll
    for (int j = 0; j < 8; j++) {
        int idx = tid + 256 * j;          // 2048 float4 = 128 rows x 64 d
        float4 v = xg[idx];
        int r = idx >> 4, d4 = (idx & 15) << 2;
        xsT[(d4 + 0) * XPAD + r] = v.x;
        xsT[(d4 + 1) * XPAD + r] = v.y;
        xsT[(d4 + 2) * XPAD + r] = v.z;
        xsT[(d4 + 3) * XPAD + r] = v.w;
    }
    const float4* wg = (const float4*)Wih0;
#pragma unroll
    for (int j = 0; j < 8; j++) {
        int idx = tid + 256 * j;          // 2048 float4 = 128 h x 64 d
        float4 v = wg[idx];
        int h = idx >> 4, d4 = (idx & 15) << 2;
        wsT[(d4 + 0) * XPAD + h] = v.x;
        wsT[(d4 + 1) * XPAD + h] = v.y;
        wsT[(d4 + 2) * XPAD + h] = v.z;
        wsT[(d4 + 3) * XPAD + h] = v.w;
    }

    int tx = tid & 15, ty = tid >> 4;
    int c0 = tx * 8, r0 = ty * 8;
    float acc[8][8];
#pragma unroll
    for (int j = 0; j < 8; j++) {
        float bb = bih0[c0 + j] + bhh0[c0 + j];
#pragma unroll
        for (int i = 0; i < 8; i++) acc[i][j] = bb;
    }
    __syncthreads();

#pragma unroll 8
    for (int k = 0; k < 64; k++) {
        float4 a0 = *(const float4*)&xsT[k * XPAD + r0];
        float4 a1 = *(const float4*)&xsT[k * XPAD + r0 + 4];
        float4 b0 = *(const float4*)&wsT[k * XPAD + c0];
        float4 b1 = *(const float4*)&wsT[k * XPAD + c0 + 4];
        float av[8] = {a0.x, a0.y, a0.z, a0.w, a1.x, a1.y, a1.z, a1.w};
        float bv[8] = {b0.x, b0.y, b0.z, b0.w, b1.x, b1.y, b1.z, b1.w};
#pragma unroll
        for (int i = 0; i < 8; i++)
#pragma unroll
            for (int j = 0; j < 8; j++)
                acc[i][j] = fmaf(av[i], bv[j], acc[i][j]);
    }

    float* og = g_xp0 + (size_t)row0 * HH;
#pragma unroll
    for (int i = 0; i < 8; i++) {
        *(float4*)&og[(size_t)(r0 + i) * HH + c0] =
            make_float4(acc[i][0], acc[i][1], acc[i][2], acc[i][3]);
        *(float4*)&og[(size_t)(r0 + i) * HH + c0 + 4] =
            make_float4(acc[i][4], acc[i][5], acc[i][6], acc[i][7]);
    }
}

// ---------------------------------------------------------------------------
// Kernel 2: sequential scan. 1 CTA per batch element, 384 threads in 3 groups:
//   group 0: layer0 recurrence (W_hh0 row in regs)
//   group 1: layer1 input projection (W_ih1 row in regs)
//   group 2: layer1 recurrence (W_hh1 row in regs)
// 1-step skew per group, one barrier per step. xp prefetched through a
// 4-deep register ring (loop unrolled x4 so ring indices are static).
__global__ void __launch_bounds__(384, 1)
scan_kernel(const float* __restrict__ Whh0, const float* __restrict__ Wih1,
            const float* __restrict__ Whh1, const float* __restrict__ bih1,
            const float* __restrict__ bhh1, const int* __restrict__ lengths) {
    __shared__ __align__(16) float h0buf[2][HH];
    __shared__ __align__(16) float h1buf[2][HH];
    __shared__ __align__(16) float p1buf[2][HH];

    int b   = blockIdx.x;
    int L   = lengths[b];
    int tid = threadIdx.x;
    int grp = tid >> 7;
    int row = tid & 127;

    const float* Wrow = (grp == 0 ? Whh0 : (grp == 1 ? Wih1 : Whh1)) + (size_t)row * HH;
    ull w[64];
#pragma unroll
    for (int j = 0; j < 64; j++) w[j] = ((const ull*)Wrow)[j];

    float bias1 = 0.f;
    if (grp == 1) bias1 = bih1[row] + bhh1[row];

    if (grp == 0) h0buf[1][row] = 0.f;   // value index -1 lives in buffer 1
    if (grp == 2) h1buf[1][row] = 0.f;

    const float* xp_base = g_xp0 + (size_t)b * TT * HH + row;
    float* h1_out_base   = g_h1  + (size_t)b * TT * HH + row;

    float xp[4];
    if (grp == 0) {
#pragma unroll
        for (int i = 0; i < 4; i++) xp[i] = (i < L) ? xp_base[(size_t)i * HH] : 0.f;
    }
    __syncthreads();

    int spad = ((L + 2) + 3) & ~3;
    for (int s0 = 0; s0 < spad; s0 += 4) {
#pragma unroll
        for (int u = 0; u < 4; u++) {
            int s = s0 + u;
            int pa = s & 1, pb = pa ^ 1;
            if (grp == 0) {
                if (s < L) {
                    float v = xp[u] + dot128(w, h0buf[pb]);   // h0 value s-1
                    h0buf[pa][row] = fast_tanh(v);            // h0 value s
                    int sn = s + 4;
                    xp[u] = (sn < L) ? xp_base[(size_t)sn * HH] : 0.f;
                }
            } else if (grp == 1) {
                if (s >= 1 && s <= L) {
                    float v = bias1 + dot128(w, h0buf[pb]);   // h0 value s-1
                    p1buf[pb][row] = v;                       // p1 value s-1
                }
            } else {
                if (s >= 2 && s <= L + 1) {
                    float v  = p1buf[pa][row] + dot128(w, h1buf[pb]); // p1[s-2], h1[s-3]
                    float hn = fast_tanh(v);
                    h1buf[pa][row] = hn;                      // h1 value s-2
                    h1_out_base[(size_t)(s - 2) * HH] = hn;
                }
            }
            __syncthreads();
        }
    }
}

// ---------------------------------------------------------------------------
// Kernel 3: out[b,t,:] = (t < L) ? h1[b,t,:] @ W_fc^T + b_fc : b_fc
// Block = 32 (b,t) rows, 256 threads = 32 outputs x 8 row-groups of 4 rows.
__global__ void __launch_bounds__(256)
fc_kernel(const float* __restrict__ Wfc, const float* __restrict__ bfc,
          const int* __restrict__ lengths, float* __restrict__ out) {
    __shared__ __align__(16) float wfcT[HH * 33];
    __shared__ __align__(16) float h1s[32 * HH];
    __shared__ float bfcs[OO];

    int tid  = threadIdx.x;
    int row0 = blockIdx.x * 32;      // 32 | TT -> whole block is one batch b
    int b = row0 / TT;
    int L = lengths[b];

    for (int idx = tid; idx < OO * HH; idx += 256) {
        int o = idx >> 7, k = idx & 127;
        wfcT[k * 33 + o] = Wfc[idx];
    }
    if (tid < OO) bfcs[tid] = bfc[tid];
    const float4* hg = (const float4*)(g_h1 + (size_t)row0 * HH);
#pragma unroll
    for (int j = 0; j < 4; j++)
        ((float4*)h1s)[tid + 256 * j] = hg[tid + 256 * j];
    __syncthreads();

    int o  = tid & 31;
    int rg = tid >> 5;               // 8 groups x 4 rows
    int tb = row0 % TT;
#pragma unroll
    for (int i = 0; i < 4; i++) {
        int r = rg * 4 + i;
        int t = tb + r;
        float res;
        if (t < L) {
            float acc = 0.f;
#pragma unroll
            for (int k = 0; k < HH; k++)
                acc = fmaf(wfcT[k * 33 + o], h1s[r * HH + k], acc);
            res = acc + bfcs[o];
        } else {
            res = bfcs[o];
        }
        out[(size_t)(row0 + r) * OO + o] = res;
    }
}

// ---------------------------------------------------------------------------
extern "C" void kernel_launch(void* const* d_in, const int* in_sizes, int n_in,
                              void* d_out, int out_size) {
    const float* x     = (const float*)d_in[0];
    const int*   len   = (const int*)  d_in[1];
    const float* Wih0  = (const float*)d_in[2];
    const float* Whh0  = (const float*)d_in[3];
    const float* bih0  = (const float*)d_in[4];
    const float* bhh0  = (const float*)d_in[5];
    const float* Wih1  = (const float*)d_in[6];
    const float* Whh1  = (const float*)d_in[7];
    const float* bih1  = (const float*)d_in[8];
    const float* bhh1  = (const float*)d_in[9];
    const float* Wfc   = (const float*)d_in[10];
    const float* bfc   = (const float*)d_in[11];
    float* out = (float*)d_out;

    static_assert(2 * 64 * XPAD * 4 == 67584, "smem size");
    cudaFuncSetAttribute(xproj_kernel, cudaFuncAttributeMaxDynamicSharedMemorySize, 67584);
    xproj_kernel<<<(BB * TT) / 128, 256, 67584>>>(x, Wih0, bih0, bhh0);
    scan_kernel<<<BB, 384>>>(Whh0, Wih1, Whh1, bih1, bhh1, len);
    fc_kernel<<<(BB * TT) / 32, 256>>>(Wfc, bfc, len, out);
}

// round 3
// speedup vs baseline: 1.5630x; 1.0840x over previous
#include <cuda_runtime.h>

#define BB 128
#define TT 2048
#define DD 64
#define HH 128
#define OO 32

typedef unsigned long long ull;

// Scratch (allocation-free rule: __device__ globals)
__device__ float g_xp0[(size_t)BB * TT * HH];  // layer0 input projection
__device__ float g_h1[(size_t)BB * TT * HH];   // layer1 hidden states

// ---------------------------------------------------------------------------
// fast tanh: ~1e-7 relative error
__device__ __forceinline__ float fast_tanh(float x) {
    float ax = fminf(fabsf(x), 9.0f);
    float e  = __expf(2.0f * ax);
    float r  = 1.0f - __fdividef(2.0f, e + 1.0f);
    return copysignf(r, x);
}

// 128-long dot product with c0 folded into the accumulator init.
// Weights in registers as 64 packed f32x2, vector from smem via LDS.128
// (broadcast). 2 accumulator chains (dep spacing 6cyc at rt3 > 4cyc latency).
__device__ __forceinline__ float dot128_c0(const ull* w, const float* v, float c0) {
    ull a0, a1 = 0ull;
    asm("mov.b64 %0, {%1, %2};" : "=l"(a0) : "f"(c0), "f"(0.0f));
    const ulonglong2* v2 = (const ulonglong2*)v;
#pragma unroll
    for (int j = 0; j < 32; j++) {
        ulonglong2 p = v2[j];
        asm("fma.rn.f32x2 %0, %1, %2, %0;" : "+l"(a0) : "l"(w[2 * j]),     "l"(p.x));
        asm("fma.rn.f32x2 %0, %1, %2, %0;" : "+l"(a1) : "l"(w[2 * j + 1]), "l"(p.y));
    }
    asm("add.rn.f32x2 %0, %0, %1;" : "+l"(a0) : "l"(a1));
    float lo = __uint_as_float((unsigned)(a0 & 0xffffffffu));
    float hi = __uint_as_float((unsigned)(a0 >> 32));
    return lo + hi;
}

// ---------------------------------------------------------------------------
// Kernel 1: xp0[b,t,h] = sum_d x[b,t,d]*W_ih0[h,d] + b_ih0[h] + b_hh0[h]
// smem-tiled GEMM, 128x128 block tile, K=64, 8x8 register tile per thread.
#define XPAD 132
__global__ void __launch_bounds__(256)
xproj_kernel(const float* __restrict__ x, const float* __restrict__ Wih0,
             const float* __restrict__ bih0, const float* __restrict__ bhh0) {
    extern __shared__ float sm[];
    float* xsT = sm;                 // [64][XPAD] : xsT[d][r]
    float* wsT = sm + 64 * XPAD;     // [64][XPAD] : wsT[d][h]
    int tid  = threadIdx.x;
    int row0 = blockIdx.x * 128;

    const float4* xg = (const float4*)(x + (size_t)row0 * DD);
#pragma unroll
    for (int j = 0; j < 8; j++) {
        int idx = tid + 256 * j;
        float4 v = xg[idx];
        int r = idx >> 4, d4 = (idx & 15) << 2;
        xsT[(d4 + 0) * XPAD + r] = v.x;
        xsT[(d4 + 1) * XPAD + r] = v.y;
        xsT[(d4 + 2) * XPAD + r] = v.z;
        xsT[(d4 + 3) * XPAD + r] = v.w;
    }
    const float4* wg = (const float4*)Wih0;
#pragma unroll
    for (int j = 0; j < 8; j++) {
        int idx = tid + 256 * j;
        float4 v = wg[idx];
        int h = idx >> 4, d4 = (idx & 15) << 2;
        wsT[(d4 + 0) * XPAD + h] = v.x;
        wsT[(d4 + 1) * XPAD + h] = v.y;
        wsT[(d4 + 2) * XPAD + h] = v.z;
        wsT[(d4 + 3) * XPAD + h] = v.w;
    }

    int tx = tid & 15, ty = tid >> 4;
    int c0 = tx * 8, r0 = ty * 8;
    float acc[8][8];
#pragma unroll
    for (int j = 0; j < 8; j++) {
        float bb = bih0[c0 + j] + bhh0[c0 + j];
#pragma unroll
        for (int i = 0; i < 8; i++) acc[i][j] = bb;
    }
    __syncthreads();

#pragma unroll 8
    for (int k = 0; k < 64; k++) {
        float4 a0 = *(const float4*)&xsT[k * XPAD + r0];
        float4 a1 = *(const float4*)&xsT[k * XPAD + r0 + 4];
        float4 b0 = *(const float4*)&wsT[k * XPAD + c0];
        float4 b1 = *(const float4*)&wsT[k * XPAD + c0 + 4];
        float av[8] = {a0.x, a0.y, a0.z, a0.w, a1.x, a1.y, a1.z, a1.w};
        float bv[8] = {b0.x, b0.y, b0.z, b0.w, b1.x, b1.y, b1.z, b1.w};
#pragma unroll
        for (int i = 0; i < 8; i++)
#pragma unroll
            for (int j = 0; j < 8; j++)
                acc[i][j] = fmaf(av[i], bv[j], acc[i][j]);
    }

    float* og = g_xp0 + (size_t)row0 * HH;
#pragma unroll
    for (int i = 0; i < 8; i++) {
        *(float4*)&og[(size_t)(r0 + i) * HH + c0] =
            make_float4(acc[i][0], acc[i][1], acc[i][2], acc[i][3]);
        *(float4*)&og[(size_t)(r0 + i) * HH + c0 + 4] =
            make_float4(acc[i][4], acc[i][5], acc[i][6], acc[i][7]);
    }
}

// ---------------------------------------------------------------------------
// Kernel 2: sequential scan, BRANCH-FREE inner body.
// 1 CTA / batch element, 384 threads, 3 groups (layer0 rec / layer1 proj /
// layer1 rec), 1-step skew per group, one barrier per step.
// All groups run every step; out-of-range results are finite garbage that
// only reaches positions masked by fc. Uninitialized-smem reads feed only
// predicated-off stores. Group behavior encoded in parity-indexed pointers
// (static after x4 unroll), FSELs and warp-uniform predicated STS/STG/LDG.
__global__ void __launch_bounds__(384, 1)
scan_kernel(const float* __restrict__ Whh0, const float* __restrict__ Wih1,
            const float* __restrict__ Whh1, const float* __restrict__ bih1,
            const float* __restrict__ bhh1, const int* __restrict__ lengths) {
    __shared__ __align__(16) float h0buf[2][HH];
    __shared__ __align__(16) float h1buf[2][HH];
    __shared__ __align__(16) float p1buf[2][HH];

    int b   = blockIdx.x;
    int L   = lengths[b];
    int tid = threadIdx.x;
    int grp = tid >> 7;
    int row = tid & 127;
    bool isg0 = (grp == 0), isg1 = (grp == 1), isg2 = (grp == 2);

    const float* Wrow = (isg0 ? Whh0 : (isg1 ? Wih1 : Whh1)) + (size_t)row * HH;
    ull w[64];
#pragma unroll
    for (int j = 0; j < 64; j++) w[j] = ((const ull*)Wrow)[j];

    // c0 ring: g0 = streamed xp values; g1 = bias (constant); g2 = 0
    const float* xp_base = g_xp0 + (size_t)b * TT * HH + row;
    float cinit = isg1 ? (bih1[row] + bhh1[row]) : 0.f;
    float xp[4];
#pragma unroll
    for (int i = 0; i < 4; i++) xp[i] = isg0 ? xp_base[(size_t)i * HH] : cinit;

    if (isg0) h0buf[1][row] = 0.f;   // value index -1 lives in buffer 1
    if (isg2) h1buf[1][row] = 0.f;

    // parity-indexed pointers (pa = s&1):
    //   g0: read h0buf[pb], write h0buf[pa]
    //   g1: read h0buf[pb], write p1buf[pb]
    //   g2: read h1buf[pb], write h1buf[pa], extra-read p1buf[pa]
    const float* vrd[2];
    float*       st[2];
    const float* prd[2];
#pragma unroll
    for (int pa = 0; pa < 2; pa++) {
        int pb = pa ^ 1;
        vrd[pa] = isg2 ? h1buf[pb] : h0buf[pb];
        st[pa]  = isg0 ? &h0buf[pa][row] : (isg1 ? &p1buf[pb][row] : &h1buf[pa][row]);
        prd[pa] = &p1buf[pa][row];
    }
    float* h1out = g_h1 + (size_t)b * TT * HH + row;

    __syncthreads();

    int spad = ((L + 2) + 3) & ~3;
    for (int s0 = 0; s0 < spad; s0 += 4) {
#pragma unroll
        for (int u = 0; u < 4; u++) {
            int s  = s0 + u;
            int pa = u & 1;                       // s0 multiple of 4 -> static
            float extra = *prd[pa];               // p1 value s-2 (g2 only)
            float d   = dot128_c0(w, vrd[pa], xp[u]);
            float pre = d + (isg2 ? extra : 0.f); // FSEL keeps NaN out of g0/g1
            float th  = fast_tanh(pre);
            float y   = isg1 ? pre : th;
            if (!isg2 || s >= 2) *st[pa] = y;     // predicated STS
            if (isg2 && s >= 2 && s - 2 < TT)     // predicated STG
                h1out[(size_t)(s - 2) * HH] = y;
            if (isg0) {                           // predicated prefetch LDG
                int nidx = s + 4; if (nidx > TT - 1) nidx = TT - 1;
                xp[u] = __ldg(&xp_base[(size_t)nidx * HH]);
            }
            __syncthreads();
        }
    }
}

// ---------------------------------------------------------------------------
// Kernel 3: out[b,t,:] = (t < L) ? h1[b,t,:] @ W_fc^T + b_fc : b_fc
__global__ void __launch_bounds__(256)
fc_kernel(const float* __restrict__ Wfc, const float* __restrict__ bfc,
          const int* __restrict__ lengths, float* __restrict__ out) {
    __shared__ __align__(16) float wfcT[HH * 33];
    __shared__ __align__(16) float h1s[32 * HH];
    __shared__ float bfcs[OO];

    int tid  = threadIdx.x;
    int row0 = blockIdx.x * 32;      // 32 | TT -> whole block is one batch b
    int b = row0 / TT;
    int L = lengths[b];

    for (int idx = tid; idx < OO * HH; idx += 256) {
        int o = idx >> 7, k = idx & 127;
        wfcT[k * 33 + o] = Wfc[idx];
    }
    if (tid < OO) bfcs[tid] = bfc[tid];
    const float4* hg = (const float4*)(g_h1 + (size_t)row0 * HH);
#pragma unroll
    for (int j = 0; j < 4; j++)
        ((float4*)h1s)[tid + 256 * j] = hg[tid + 256 * j];
    __syncthreads();

    int o  = tid & 31;
    int rg = tid >> 5;               // 8 groups x 4 rows
    int tb = row0 % TT;
#pragma unroll
    for (int i = 0; i < 4; i++) {
        int r = rg * 4 + i;
        int t = tb + r;
        float res;
        if (t < L) {
            float acc = 0.f;
#pragma unroll
            for (int k = 0; k < HH; k++)
                acc = fmaf(wfcT[k * 33 + o], h1s[r * HH + k], acc);
            res = acc + bfcs[o];
        } else {
            res = bfcs[o];
        }
        out[(size_t)(row0 + r) * OO + o] = res;
    }
}

// ---------------------------------------------------------------------------
extern "C" void kernel_launch(void* const* d_in, const int* in_sizes, int n_in,
                              void* d_out, int out_size) {
    const float* x     = (const float*)d_in[0];
    const int*   len   = (const int*)  d_in[1];
    const float* Wih0  = (const float*)d_in[2];
    const float* Whh0  = (const float*)d_in[3];
    const float* bih0  = (const float*)d_in[4];
    const float* bhh0  = (const float*)d_in[5];
    const float* Wih1  = (const float*)d_in[6];
    const float* Whh1  = (const float*)d_in[7];
    const float* bih1  = (const float*)d_in[8];
    const float* bhh1  = (const float*)d_in[9];
    const float* Wfc   = (const float*)d_in[10];
    const float* bfc   = (const float*)d_in[11];
    float* out = (float*)d_out;

    static_assert(2 * 64 * XPAD * 4 == 67584, "smem size");
    cudaFuncSetAttribute(xproj_kernel, cudaFuncAttributeMaxDynamicSharedMemorySize, 67584);
    xproj_kernel<<<(BB * TT) / 128, 256, 67584>>>(x, Wih0, bih0, bhh0);
    scan_kernel<<<BB, 384>>>(Whh0, Wih1, Whh1, bih1, bhh1, len);
    fc_kernel<<<(BB * TT) / 32, 256>>>(Wfc, bfc, len, out);
}